// round 3
// baseline (speedup 1.0000x reference)
#include <cuda_runtime.h>

#define BB 256
#define TT 512
#define II 64
#define HH 512
#define OO 24

#define BM 32
#define HN 32
#define NHT (HH/HN)            // 16
#define NBLOCKS ((BB/BM)*NHT)  // 128
#define NTHREADS 256

#define S2 34                  // float2 row stride for weight tiles (even -> 16B-aligned float4 loads)

#define WS2_FLOATS ((HH/2)*S2*2)   // 17408
#define WI2_FLOATS ((II/2)*S2*2)   // 2176
#define SMEM_FLOATS (WS2_FLOATS + WI2_FLOATS + BM*HH + BM*II + HN)
#define SMEM_BYTES  (SMEM_FLOATS * 4)   // 152192

// Ping-pong hidden state (no allocations allowed)
__device__ float g_h[2][BB * HH];

// Packed dual-FMA: d = a*b + c lanewise (fp32x2). ptxas never emits this from C++.
__device__ __forceinline__ float2 ffma2(float2 a, float2 b, float2 c) {
    unsigned long long A, B, C, D;
    asm("mov.b64 %0, {%1, %2};" : "=l"(A) : "f"(a.x), "f"(a.y));
    asm("mov.b64 %0, {%1, %2};" : "=l"(B) : "f"(b.x), "f"(b.y));
    asm("mov.b64 %0, {%1, %2};" : "=l"(C) : "f"(c.x), "f"(c.y));
    asm("fma.rn.f32x2 %0, %1, %2, %3;" : "=l"(D) : "l"(A), "l"(B), "l"(C));
    float2 d;
    asm("mov.b64 {%0, %1}, %2;" : "=f"(d.x), "=f"(d.y) : "l"(D));
    return d;
}

// One timestep: h_t = relu(x_t @ W_ih^T + b + h_{t-1} @ W_hh^T)
__global__ void __launch_bounds__(NTHREADS, 1)
rnn_step_kernel(const float* __restrict__ x,
                const float* __restrict__ W_ih,
                const float* __restrict__ W_hh,
                const float* __restrict__ b_ih,
                const float* __restrict__ b_hh,
                int t)
{
    extern __shared__ float smem[];
    float2* Ws2 = (float2*)smem;                               // [HH/2][S2]: (w[k],w[k+1]) per col
    float2* Wi2 = (float2*)(smem + WS2_FLOATS);                // [II/2][S2]
    float*  As  = smem + WS2_FLOATS + WI2_FLOATS;              // [BM][HH] h_{t-1} tile
    float*  Xs  = As + BM * HH;                                // [BM][II] x_t tile
    float*  bsm = Xs + BM * II;                                // [HN]

    const int tid = threadIdx.x;
    const int bt  = blockIdx.x / NHT;
    const int ht  = blockIdx.x % NHT;
    const int b0  = bt * BM;
    const int h0  = ht * HN;

    const float* gprev = g_h[1 - (t & 1)];
    float*       gnew  = g_h[t & 1];

    // --- Stage W_hh tile: Ws2[k/2][hh] = (W_hh[h0+hh][k], W_hh[h0+hh][k+1]) ---
    for (int idx = tid; idx < HN * (HH / 4); idx += NTHREADS) {
        int k4 = idx & (HH / 4 - 1);
        int hh = idx >> 7;                      // idx / 128
        float4 w = *(const float4*)&W_hh[(size_t)(h0 + hh) * HH + k4 * 4];
        Ws2[(2 * k4)     * S2 + hh] = make_float2(w.x, w.y);
        Ws2[(2 * k4 + 1) * S2 + hh] = make_float2(w.z, w.w);
    }
    // --- Stage W_ih tile ---
    for (int idx = tid; idx < HN * (II / 4); idx += NTHREADS) {
        int i4 = idx & (II / 4 - 1);
        int hh = idx >> 4;                      // idx / 16
        float4 w = *(const float4*)&W_ih[(size_t)(h0 + hh) * II + i4 * 4];
        Wi2[(2 * i4)     * S2 + hh] = make_float2(w.x, w.y);
        Wi2[(2 * i4 + 1) * S2 + hh] = make_float2(w.z, w.w);
    }
    if (tid < HN) bsm[tid] = b_ih[h0 + tid] + b_hh[h0 + tid];

    // --- Stage h_{t-1} tile (contiguous 64KB copy) ---
    if (t > 0) {
        const float4* src = (const float4*)(gprev + (size_t)b0 * HH);
        float4* dst = (float4*)As;
        for (int idx = tid; idx < BM * HH / 4; idx += NTHREADS) dst[idx] = src[idx];
    }
    // --- Stage x_t tile ---
    for (int idx = tid; idx < BM * (II / 4); idx += NTHREADS) {
        int i4 = idx & (II / 4 - 1);
        int bl = idx >> 4;
        ((float4*)Xs)[idx] = *(const float4*)&x[((size_t)(b0 + bl) * TT + t) * II + i4 * 4];
    }
    __syncthreads();

    // --- Thread micro-tile: 2 batch rows x 2 hidden cols; even/odd k in f32x2 lanes ---
    const int hh = (tid & 15) * 2;
    const int bb = (tid >> 4) * 2;

    float2 acc00 = make_float2(0.f, 0.f), acc01 = make_float2(0.f, 0.f);
    float2 acc10 = make_float2(0.f, 0.f), acc11 = make_float2(0.f, 0.f);

    // Input projection
    {
        const float2* a0p = (const float2*)&Xs[bb * II];
        const float2* a1p = (const float2*)&Xs[(bb + 1) * II];
        #pragma unroll
        for (int i2 = 0; i2 < II / 2; ++i2) {
            float2 a0 = a0p[i2], a1 = a1p[i2];
            float4 w = *(const float4*)&Wi2[i2 * S2 + hh];
            float2 w0 = make_float2(w.x, w.y);
            float2 w1 = make_float2(w.z, w.w);
            acc00 = ffma2(a0, w0, acc00);
            acc01 = ffma2(a0, w1, acc01);
            acc10 = ffma2(a1, w0, acc10);
            acc11 = ffma2(a1, w1, acc11);
        }
    }
    // Recurrent projection
    if (t > 0) {
        const float2* a0p = (const float2*)&As[bb * HH];
        const float2* a1p = (const float2*)&As[(bb + 1) * HH];
        #pragma unroll 8
        for (int k2 = 0; k2 < HH / 2; ++k2) {
            float2 a0 = a0p[k2], a1 = a1p[k2];
            float4 w = *(const float4*)&Ws2[k2 * S2 + hh];
            float2 w0 = make_float2(w.x, w.y);
            float2 w1 = make_float2(w.z, w.w);
            acc00 = ffma2(a0, w0, acc00);
            acc01 = ffma2(a0, w1, acc01);
            acc10 = ffma2(a1, w0, acc10);
            acc11 = ffma2(a1, w1, acc11);
        }
    }

    const float bias0 = bsm[hh];
    const float bias1 = bsm[hh + 1];
    float2 r0 = make_float2(fmaxf(acc00.x + acc00.y + bias0, 0.f),
                            fmaxf(acc01.x + acc01.y + bias1, 0.f));
    float2 r1 = make_float2(fmaxf(acc10.x + acc10.y + bias0, 0.f),
                            fmaxf(acc11.x + acc11.y + bias1, 0.f));
    *(float2*)&gnew[(size_t)(b0 + bb)     * HH + h0 + hh] = r0;
    *(float2*)&gnew[(size_t)(b0 + bb + 1) * HH + h0 + hh] = r1;
}

// Epilogue: out = h_T @ fc_w^T + fc_b
__global__ void fc_kernel(const float* __restrict__ fc_w,
                          const float* __restrict__ fc_b,
                          float* __restrict__ out)
{
    int p = blockIdx.x * blockDim.x + threadIdx.x;   // 0..6143
    int b = p / OO, o = p % OO;
    const float* h = g_h[(TT - 1) & 1] + (size_t)b * HH;
    const float* w = fc_w + (size_t)o * HH;
    float s = fc_b[o];
    #pragma unroll 8
    for (int k = 0; k < HH; ++k) s = fmaf(h[k], __ldg(&w[k]), s);
    out[p] = s;
}

extern "C" void kernel_launch(void* const* d_in, const int* in_sizes, int n_in,
                              void* d_out, int out_size)
{
    // Positional defaults (setup_inputs dict order)...
    const float* x    = (const float*)d_in[0];
    const float* W_ih = (const float*)d_in[1];
    const float* W_hh = (const float*)d_in[2];
    const float* b_ih = (const float*)d_in[3];
    const float* b_hh = (const float*)d_in[4];
    const float* fc_w = (const float*)d_in[5];
    const float* fc_b = (const float*)d_in[6];
    // ...overridden by unambiguous size-based identification.
    int nb = 0;
    for (int i = 0; i < n_in; ++i) {
        const float* p = (const float*)d_in[i];
        switch (in_sizes[i]) {
            case BB * TT * II: x    = p; break;   // 8388608
            case HH * II:      W_ih = p; break;   // 32768
            case HH * HH:      W_hh = p; break;   // 262144
            case OO * HH:      fc_w = p; break;   // 12288
            case OO:           fc_b = p; break;   // 24
            case HH:           if (nb++ == 0) b_ih = p; else b_hh = p; break; // symmetric
            default: break;
        }
    }
    float* out = (float*)d_out;

    cudaFuncSetAttribute(rnn_step_kernel,
                         cudaFuncAttributeMaxDynamicSharedMemorySize, SMEM_BYTES);

    for (int t = 0; t < TT; ++t)
        rnn_step_kernel<<<NBLOCKS, NTHREADS, SMEM_BYTES>>>(x, W_ih, W_hh, b_ih, b_hh, t);

    fc_kernel<<<(BB * OO) / NTHREADS, NTHREADS>>>(fc_w, fc_b, out);
}